// round 15
// baseline (speedup 1.0000x reference)
#include <cuda_runtime.h>
#include <cuda_bf16.h>
#include <cuda_fp16.h>
#include <stdint.h>
#include <math.h>

// Problem constants
#define S_TOK 3072
#define HID 1152
#define NH 16
#define HD 72
#define MLP_DIM 4304
#define MLP_P2 4352           // MLP_DIM padded to multiple of 64 (zeros in pad)
#define QKV_N (3*HID)         // 3456
#define EPS 1e-5f

// ---------------- scratch (allocation-free: __device__ globals, zero-init) ----
__device__ float g_x2[S_TOK*HID];
__device__ unsigned short g_qkvh[S_TOK*QKV_N];
__device__ unsigned short g_Qr[NH*S_TOK*80];
__device__ unsigned short g_Kr[NH*S_TOK*80];
__device__ unsigned short g_Vt[NH*HD*S_TOK];
__device__ unsigned short g_h0h[S_TOK*HID];
__device__ unsigned short g_attnh[S_TOK*HID];
__device__ unsigned short g_h1h[S_TOK*HID];
__device__ unsigned short g_mlph[S_TOK*MLP_P2];
__device__ unsigned short g_wqkvth[QKV_N*HID];
__device__ unsigned short g_woth[HID*HID];
__device__ unsigned short g_w1th[MLP_DIM*HID];
__device__ unsigned short g_w2th[HID*MLP_P2];

// ---------------- PTX helpers ----------------
__device__ __forceinline__ uint32_t smem_u32(const void* p) {
    uint32_t a;
    asm("{ .reg .u64 t; cvta.to.shared.u64 t, %1; cvt.u32.u64 %0, t; }"
        : "=r"(a) : "l"(p));
    return a;
}

#define MMA_F16(C, A, B0, B1)                                               \
    asm volatile("mma.sync.aligned.m16n8k16.row.col.f32.f16.f16.f32 "       \
                 "{%0,%1,%2,%3}, {%4,%5,%6,%7}, {%8,%9}, {%0,%1,%2,%3};\n"  \
                 : "+f"((C)[0]), "+f"((C)[1]), "+f"((C)[2]), "+f"((C)[3])   \
                 : "r"((A)[0]), "r"((A)[1]), "r"((A)[2]), "r"((A)[3]),      \
                   "r"(B0), "r"(B1))

#define LDSM_X4(R, a)                                                          \
    asm volatile("ldmatrix.sync.aligned.m8n8.x4.shared.b16 {%0,%1,%2,%3}, [%4];" \
                 : "=r"((R)[0]), "=r"((R)[1]), "=r"((R)[2]), "=r"((R)[3])      \
                 : "r"(a))
#define LDSM_X2(R, a)                                                          \
    asm volatile("ldmatrix.sync.aligned.m8n8.x2.shared.b16 {%0,%1}, [%2];"     \
                 : "=r"((R)[0]), "=r"((R)[1]) : "r"(a))

__device__ __forceinline__ void cp_async16(unsigned dst, const void* src, bool valid) {
    int sz = valid ? 16 : 0;
    asm volatile("cp.async.cg.shared.global [%0], [%1], 16, %2;"
                 :: "r"(dst), "l"(src), "r"(sz));
}
#define CP_COMMIT asm volatile("cp.async.commit_group;")
#define CP_WAIT1  asm volatile("cp.async.wait_group 1;")

__device__ __forceinline__ float gelu_fast(float v) {
    float u = 0.7978845608028654f * (v + 0.044715f * v * v * v);
    return v / (1.0f + __expf(-2.0f * u));
}

// ---------------- LayerNorm (warp-shuffle reduce, fp16 out) -----------------
__global__ void ln_kernel(const float* __restrict__ x, const float* __restrict__ g,
                          const float* __restrict__ b, __half* __restrict__ y) {
    __shared__ float row[HID];
    __shared__ float ws[8], wss[8], bc[2];
    int r = blockIdx.x;
    int tid = threadIdx.x, lane = tid & 31, warp = tid >> 5;
    float s = 0.f, ss = 0.f;
    for (int i = tid; i < HID; i += 256) {
        float v = x[(size_t)r*HID + i];
        row[i] = v;
        s += v; ss += v*v;
    }
#pragma unroll
    for (int o = 16; o > 0; o >>= 1) {
        s  += __shfl_xor_sync(0xffffffffu, s, o);
        ss += __shfl_xor_sync(0xffffffffu, ss, o);
    }
    if (lane == 0) { ws[warp] = s; wss[warp] = ss; }
    __syncthreads();
    if (warp == 0) {
        float a = (lane < 8) ? ws[lane] : 0.f;
        float c = (lane < 8) ? wss[lane] : 0.f;
#pragma unroll
        for (int o = 4; o > 0; o >>= 1) {
            a += __shfl_xor_sync(0xffffffffu, a, o, 8);
            c += __shfl_xor_sync(0xffffffffu, c, o, 8);
        }
        if (lane == 0) {
            float mu = a * (1.0f/HID);
            float var = c * (1.0f/HID) - mu*mu;
            bc[0] = mu; bc[1] = rsqrtf(var + EPS);
        }
    }
    __syncthreads();
    float mu = bc[0], rstd = bc[1];
    for (int i = tid; i < HID; i += 256) {
        y[(size_t)r*HID + i] = __float2half_rn((row[i] - mu) * rstd * g[i] + b[i]);
    }
}

// ---------------- fused transpose of all 4 weights ([K][N]->[N][K], fp16) ----
#define TG0 (108*36)         // wqkv: N=3456 -> 108 x-tiles, K=1152 -> 36 y
#define TG1 (36*36)          // wo
#define TG2 (135*36)         // w1: N=4304 -> 135, K=1152
#define TG3 (36*135)         // w2: N=1152 -> 36, K=4304 -> 135
#define TG_ALL (TG0+TG1+TG2+TG3)

__global__ void transpose_all(const float* __restrict__ i0, __half* __restrict__ o0,
                              const float* __restrict__ i1, __half* __restrict__ o1,
                              const float* __restrict__ i2, __half* __restrict__ o2,
                              const float* __restrict__ i3, __half* __restrict__ o3) {
    __shared__ float t[32][33];
    int id = blockIdx.x;
    const float* in; __half* out; int K, N, out_ld, nx;
    if (id < TG0)            { in=i0; out=o0; K=HID;     N=QKV_N;   out_ld=HID;    nx=108; }
    else if (id < TG0+TG1)   { id-=TG0;         in=i1; out=o1; K=HID;     N=HID;     out_ld=HID;    nx=36; }
    else if (id < TG0+TG1+TG2){ id-=TG0+TG1;    in=i2; out=o2; K=HID;     N=MLP_DIM; out_ld=HID;    nx=135; }
    else                     { id-=TG0+TG1+TG2; in=i3; out=o3; K=MLP_DIM; N=HID;     out_ld=MLP_P2; nx=36; }
    int kb = (id/nx)*32, nb = (id%nx)*32;
    int x = threadIdx.x, y = threadIdx.y;   // 32 x 8
#pragma unroll
    for (int i = 0; i < 32; i += 8) {
        int k = kb + y + i, n = nb + x;
        t[y+i][x] = (k < K && n < N) ? in[(size_t)k*N + n] : 0.f;
    }
    __syncthreads();
#pragma unroll
    for (int i = 0; i < 32; i += 8) {
        int n = nb + y + i, k = kb + x;
        if (n < N && k < K) out[(size_t)n*out_ld + k] = __float2half_rn(t[x][y+i]);
    }
}

// ---------------- rope prep: qkvh -> Qr/Kr (rope'd, [h][tok][80]) + Vt ------
#define VS_P 82
__global__ void rope_prep(const __half* __restrict__ qkv, const float* __restrict__ fc,
                          __half* __restrict__ Qr, __half* __restrict__ Kr,
                          __half* __restrict__ Vt) {
    __shared__ __half vs[128*VS_P];
    int tid = threadIdx.x;
    int h = blockIdx.y, t0 = blockIdx.x*128;

    for (int t = tid; t < 128*9; t += 256) {
        int row = t/9, ch = t - row*9;
        int tok = t0 + row, d0 = ch*8;
        float4 cA = *(const float4*)&fc[(size_t)tok*HD + d0];
        float4 cB = *(const float4*)&fc[(size_t)tok*HD + d0 + 4];
        {
            uint4 raw = *(const uint4*)&qkv[(size_t)tok*QKV_N + h*HD + d0];
            float2 f0 = __half22float2(*(__half2*)&raw.x);
            float2 f1 = __half22float2(*(__half2*)&raw.y);
            float2 f2 = __half22float2(*(__half2*)&raw.z);
            float2 f3 = __half22float2(*(__half2*)&raw.w);
            uint4 o;
            *(__half2*)&o.x = __floats2half2_rn(f0.x*cA.x - f0.y*cA.y, f0.x*cA.y + f0.y*cA.x);
            *(__half2*)&o.y = __floats2half2_rn(f1.x*cA.z - f1.y*cA.w, f1.x*cA.w + f1.y*cA.z);
            *(__half2*)&o.z = __floats2half2_rn(f2.x*cB.x - f2.y*cB.y, f2.x*cB.y + f2.y*cB.x);
            *(__half2*)&o.w = __floats2half2_rn(f3.x*cB.z - f3.y*cB.w, f3.x*cB.w + f3.y*cB.z);
            *(uint4*)&Qr[((size_t)h*S_TOK + tok)*80 + d0] = o;
        }
        {
            uint4 raw = *(const uint4*)&qkv[(size_t)tok*QKV_N + HID + h*HD + d0];
            float2 f0 = __half22float2(*(__half2*)&raw.x);
            float2 f1 = __half22float2(*(__half2*)&raw.y);
            float2 f2 = __half22float2(*(__half2*)&raw.z);
            float2 f3 = __half22float2(*(__half2*)&raw.w);
            uint4 o;
            *(__half2*)&o.x = __floats2half2_rn(f0.x*cA.x - f0.y*cA.y, f0.x*cA.y + f0.y*cA.x);
            *(__half2*)&o.y = __floats2half2_rn(f1.x*cA.z - f1.y*cA.w, f1.x*cA.w + f1.y*cA.z);
            *(__half2*)&o.z = __floats2half2_rn(f2.x*cB.x - f2.y*cB.y, f2.x*cB.y + f2.y*cB.x);
            *(__half2*)&o.w = __floats2half2_rn(f3.x*cB.z - f3.y*cB.w, f3.x*cB.w + f3.y*cB.z);
            *(uint4*)&Kr[((size_t)h*S_TOK + tok)*80 + d0] = o;
        }
    }
    if (tid < 128) {
        int tok = t0 + tid;
        *(uint4*)&Qr[((size_t)h*S_TOK + tok)*80 + 72] = make_uint4(0,0,0,0);
        *(uint4*)&Kr[((size_t)h*S_TOK + tok)*80 + 72] = make_uint4(0,0,0,0);
    }
    for (int t = tid; t < 128*9; t += 256) {
        int row = t/9, ch = t - row*9;
        int d0 = ch*8;
        uint4 raw = *(const uint4*)&qkv[(size_t)(t0+row)*QKV_N + 2*HID + h*HD + d0];
        uint32_t* w = (uint32_t*)&vs[row*VS_P + d0];
        w[0] = raw.x; w[1] = raw.y; w[2] = raw.z; w[3] = raw.w;
    }
    __syncthreads();
    for (int t = tid; t < HD*16; t += 256) {
        int d = t >> 4, cg = t & 15;
        int tok = cg*8;
        __half tmp[8];
#pragma unroll
        for (int i = 0; i < 8; i++) tmp[i] = vs[(tok+i)*VS_P + d];
        *(uint4*)&Vt[((size_t)h*HD + d)*S_TOK + t0 + tok] = *(uint4*)tmp;
    }
}

// ---------------- fp16 GEMM 128x128, 3-stage cp.async (QKV / MLP1) ----------
#define GBK 64
#define TILE_B (128*128)
#define STAGE_B (2*TILE_B)
#define NSTAGE 3
#define GEMM_SMEM (NSTAGE*STAGE_B)   // 98304

__global__ void __launch_bounds__(256, 2)
hgemm(const __half* __restrict__ A, int ldA,
      const __half* __restrict__ Bt, int ldB,
      const float* __restrict__ bias, const float* __restrict__ residual,
      void* __restrict__ Cv, int ldC, int N, int NIT, int mode) {
    extern __shared__ char smg[];
    unsigned sbase = smem_u32(smg);
    int tid = threadIdx.x, warp = tid >> 5, lane = tid & 31;
    int g = lane >> 2, tg = lane & 3;
    int wy = warp >> 1, wx = warp & 1;
    int m0 = blockIdx.y*128, n0 = blockIdx.x*128;

    float c[2][8][4];
#pragma unroll
    for (int mt = 0; mt < 2; mt++)
#pragma unroll
        for (int nt = 0; nt < 8; nt++)
#pragma unroll
            for (int i = 0; i < 4; i++) c[mt][nt][i] = 0.f;

    auto stage = [&](int it, int buf) {
        int k0 = it*GBK;
        unsigned sA = sbase + buf*STAGE_B;
        unsigned sB = sA + TILE_B;
#pragma unroll
        for (int i = 0; i < 4; i++) {
            int t = tid + i*256;
            int row = t >> 3, ch = t & 7;
            unsigned off = (unsigned)(row*128) + ((unsigned)(ch ^ (row & 7)) << 4);
            cp_async16(sA + off, A + (size_t)(m0+row)*ldA + k0 + ch*8, true);
            int n = n0 + row;
            bool v = (n < N);
            cp_async16(sB + off, Bt + (size_t)(v ? n : 0)*ldB + k0 + ch*8, v);
        }
    };

    stage(0, 0); CP_COMMIT;
    if (NIT > 1) stage(1, 1);
    CP_COMMIT;

    unsigned hi = (unsigned)(lane >> 4);
    unsigned aoff[2], amask[2], boff[4], bmask[4];
#pragma unroll
    for (int mt = 0; mt < 2; mt++) {
        int r = wy*32 + mt*16 + (lane & 15);
        aoff[mt] = (unsigned)(r*128); amask[mt] = (unsigned)(r & 7);
    }
#pragma unroll
    for (int p = 0; p < 4; p++) {
        int r = wx*64 + p*16 + (lane & 15);
        boff[p] = (unsigned)(r*128); bmask[p] = (unsigned)(r & 7);
    }

    for (int it = 0; it < NIT; it++) {
        CP_WAIT1;
        __syncthreads();
        if (it + 2 < NIT) stage(it+2, (it+2)%NSTAGE);
        CP_COMMIT;
        unsigned sA = sbase + (it%NSTAGE)*STAGE_B;
        unsigned sB = sA + TILE_B;
#pragma unroll
        for (int s = 0; s < 4; s++) {
            unsigned ci = (unsigned)(s*2) + hi;
            unsigned a[2][4], b[4][4];
#pragma unroll
            for (int mt = 0; mt < 2; mt++)
                LDSM_X4(a[mt], sA + aoff[mt] + ((ci ^ amask[mt]) << 4));
#pragma unroll
            for (int p = 0; p < 4; p++)
                LDSM_X4(b[p], sB + boff[p] + ((ci ^ bmask[p]) << 4));
#pragma unroll
            for (int mt = 0; mt < 2; mt++)
#pragma unroll
                for (int p = 0; p < 4; p++) {
                    MMA_F16(c[mt][2*p],   a[mt], b[p][0], b[p][2]);
                    MMA_F16(c[mt][2*p+1], a[mt], b[p][1], b[p][3]);
                }
        }
    }

    float* Cf = (float*)Cv;
    __half* Ch = (__half*)Cv;
#pragma unroll
    for (int mt = 0; mt < 2; mt++) {
        int row0 = m0 + wy*32 + mt*16 + g;
#pragma unroll
        for (int nt = 0; nt < 8; nt++) {
            int col = n0 + wx*64 + nt*8 + tg*2;
            if (col >= N) continue;
#pragma unroll
            for (int hf = 0; hf < 2; hf++) {
                int r = row0 + hf*8;
                float v0 = c[mt][nt][hf*2+0] + bias[col];
                float v1 = c[mt][nt][hf*2+1] + bias[col+1];
                if (mode == 1) {
                    v0 += residual[(size_t)r*ldC + col];
                    v1 += residual[(size_t)r*ldC + col + 1];
                    *(float2*)&Cf[(size_t)r*ldC + col] = make_float2(v0, v1);
                } else if (mode == 2) {
                    *(__half2*)&Ch[(size_t)r*ldC + col] =
                        __floats2half2_rn(gelu_fast(v0), gelu_fast(v1));
                } else if (mode == 3) {
                    *(__half2*)&Ch[(size_t)r*ldC + col] = __floats2half2_rn(v0, v1);
                } else {
                    *(float2*)&Cf[(size_t)r*ldC + col] = make_float2(v0, v1);
                }
            }
        }
    }
}

// ---------------- fp16 GEMM 64x128 (Wo / MLP2: small-N, wave-friendly) ------
#define T64_A (64*128)               // 8192 B
#define T64_B (128*128)              // 16384 B
#define STAGE64 (T64_A + T64_B)      // 24576
#define GEMM64_SMEM (NSTAGE*STAGE64) // 73728

__global__ void __launch_bounds__(256, 2)
hgemm64(const __half* __restrict__ A, int ldA,
        const __half* __restrict__ Bt, int ldB,
        const float* __restrict__ bias, const float* __restrict__ residual,
        void* __restrict__ Cv, int ldC, int N, int NIT, int mode) {
    extern __shared__ char smg[];
    unsigned sbase = smem_u32(smg);
    int tid = threadIdx.x, warp = tid >> 5, lane = tid & 31;
    int g = lane >> 2, tg = lane & 3;
    int wy = warp >> 2, wx = warp & 3;      // 2 x 4 warps, 32x32 warp tiles
    int m0 = blockIdx.y*64, n0 = blockIdx.x*128;

    float c[2][4][4];
#pragma unroll
    for (int mt = 0; mt < 2; mt++)
#pragma unroll
        for (int nt = 0; nt < 4; nt++)
#pragma unroll
            for (int i = 0; i < 4; i++) c[mt][nt][i] = 0.f;

    auto stage = [&](int it, int buf) {
        int k0 = it*GBK;
        unsigned sA = sbase + buf*STAGE64;
        unsigned sB = sA + T64_A;
#pragma unroll
        for (int i = 0; i < 2; i++) {           // A: 64 rows x 8 chunks
            int t = tid + i*256;
            int row = t >> 3, ch = t & 7;
            unsigned off = (unsigned)(row*128) + ((unsigned)(ch ^ (row & 7)) << 4);
            cp_async16(sA + off, A + (size_t)(m0+row)*ldA + k0 + ch*8, true);
        }
#pragma unroll
        for (int i = 0; i < 4; i++) {           // B: 128 rows x 8 chunks
            int t = tid + i*256;
            int row = t >> 3, ch = t & 7;
            unsigned off = (unsigned)(row*128) + ((unsigned)(ch ^ (row & 7)) << 4);
            int n = n0 + row;
            bool v = (n < N);
            cp_async16(sB + off, Bt + (size_t)(v ? n : 0)*ldB + k0 + ch*8, v);
        }
    };

    stage(0, 0); CP_COMMIT;
    if (NIT > 1) stage(1, 1);
    CP_COMMIT;

    unsigned hi = (unsigned)(lane >> 4);
    unsigned aoff[2], amask[2], boff[2], bmask[2];
#pragma unroll
    for (int mt = 0; mt < 2; mt++) {
        int r = wy*32 + mt*16 + (lane & 15);
        aoff[mt] = (unsigned)(r*128); amask[mt] = (unsigned)(r & 7);
    }
#pragma unroll
    for (int p = 0; p < 2; p++) {
        int r = wx*32 + p*16 + (lane & 15);
        boff[p] = (unsigned)(r*128); bmask[p] = (unsigned)(r & 7);
    }

    for (int it = 0; it < NIT; it++) {
        CP_WAIT1;
        __syncthreads();
        if (it + 2 < NIT) stage(it+2, (it+2)%NSTAGE);
        CP_COMMIT;
        unsigned sA = sbase + (it%NSTAGE)*STAGE64;
        unsigned sB = sA + T64_A;
#pragma unroll
        for (int s = 0; s < 4; s++) {
            unsigned ci = (unsigned)(s*2) + hi;
            unsigned a[2][4], b[2][4];
#pragma unroll
            for (int mt = 0; mt < 2; mt++)
                LDSM_X4(a[mt], sA + aoff[mt] + ((ci ^ amask[mt]) << 4));
#pragma unroll
            for (int p = 0; p < 2; p++)
                LDSM_X4(b[p], sB + boff[p] + ((ci ^ bmask[p]) << 4));
#pragma unroll
            for (int mt = 0; mt < 2; mt++)
#pragma unroll
                for (int p = 0; p < 2; p++) {
                    MMA_F16(c[mt][2*p],   a[mt], b[p][0], b[p][2]);
                    MMA_F16(c[mt][2*p+1], a[mt], b[p][1], b[p][3]);
                }
        }
    }

    float* Cf = (float*)Cv;
    __half* Ch = (__half*)Cv;
#pragma unroll
    for (int mt = 0; mt < 2; mt++) {
        int row0 = m0 + wy*32 + mt*16 + g;
#pragma unroll
        for (int nt = 0; nt < 4; nt++) {
            int col = n0 + wx*32 + nt*8 + tg*2;
            if (col >= N) continue;
#pragma unroll
            for (int hf = 0; hf < 2; hf++) {
                int r = row0 + hf*8;
                float v0 = c[mt][nt][hf*2+0] + bias[col];
                float v1 = c[mt][nt][hf*2+1] + bias[col+1];
                if (mode == 1) {
                    v0 += residual[(size_t)r*ldC + col];
                    v1 += residual[(size_t)r*ldC + col + 1];
                    *(float2*)&Cf[(size_t)r*ldC + col] = make_float2(v0, v1);
                } else if (mode == 2) {
                    *(__half2*)&Ch[(size_t)r*ldC + col] =
                        __floats2half2_rn(gelu_fast(v0), gelu_fast(v1));
                } else if (mode == 3) {
                    *(__half2*)&Ch[(size_t)r*ldC + col] = __floats2half2_rn(v0, v1);
                } else {
                    *(float2*)&Cf[(size_t)r*ldC + col] = make_float2(v0, v1);
                }
            }
        }
    }
}

// ---------------- attention: double-buffered K/V prefetch -------------------
#define AQ2 128
#define AK2 64
#define QKS_H 88
#define PVS_H 72
#define KBUF_H (AK2*QKS_H)
#define VBUF_H (HD*PVS_H)

__device__ __forceinline__ int seg_of(int t, const int* offs) {
    int s = 0;
#pragma unroll
    for (int i = 1; i <= 6; i++) if (offs[i] <= t) s = i;
    return s;
}

#define ATTN_SMEM ((AQ2*QKS_H + 2*KBUF_H + 2*VBUF_H + AQ2*PVS_H)*2 + (64+8)*4)

__global__ void __launch_bounds__(256)
attn2_kernel(const __half* __restrict__ Qr, const __half* __restrict__ Kr,
             const __half* __restrict__ Vt, const int* __restrict__ offs,
             __half* __restrict__ out) {
    extern __shared__ char sm[];
    __half* Qh = (__half*)sm;
    __half* Ph = Qh + AQ2*QKS_H + 2*KBUF_H + 2*VBUF_H;
    int* segk  = (int*)(Ph + AQ2*PVS_H);
    int* soffs = segk + 64;

    unsigned sbase = smem_u32(sm);
    unsigned uQ = sbase;
    unsigned uK = uQ + AQ2*QKS_H*2;
    unsigned uV = uK + 2*KBUF_H*2;
    unsigned uP = uV + 2*VBUF_H*2;

    int tid = threadIdx.x, warp = tid >> 5, lane = tid & 31;
    int g = lane >> 2, tg = lane & 3;
    int h = blockIdx.y, q0 = blockIdx.x*AQ2;

    if (tid < 7) soffs[tid] = offs[tid];

    auto stageKV = [&](int j0, int buf) {
        const __half* ksrc = Kr + ((size_t)h*S_TOK + j0)*80;
        unsigned kd = uK + (unsigned)buf*KBUF_H*2;
        for (int t = tid; t < AK2*10; t += 256) {
            int row = t/10, ch = t - row*10;
            cp_async16(kd + (unsigned)(row*QKS_H*2 + ch*16), ksrc + row*80 + ch*8, true);
        }
        const __half* vsrc = Vt + (size_t)h*HD*S_TOK + j0;
        unsigned vd = uV + (unsigned)buf*VBUF_H*2;
        for (int t = tid; t < HD*8; t += 256) {
            int d = t >> 3, cg = t & 7;
            cp_async16(vd + (unsigned)(d*PVS_H*2 + cg*16), vsrc + (size_t)d*S_TOK + cg*8, true);
        }
    };

    {
        const __half* qsrc = Qr + ((size_t)h*S_TOK + q0)*80;
        for (int t = tid; t < AQ2*10; t += 256) {
            int row = t/10, ch = t - row*10;
            cp_async16(uQ + (unsigned)(row*QKS_H*2 + ch*16), qsrc + row*80 + ch*8, true);
        }
        stageKV(0, 0);
        CP_COMMIT;
    }
    __syncthreads();

    int r1 = warp*16 + g, r2 = r1 + 8;
    int sq1 = seg_of(q0 + r1, soffs);
    int sq2 = seg_of(q0 + r2, soffs);

    float m1 = -1e30f, m2 = -1e30f, l1 = 0.f, l2 = 0.f;
    float co[9][4];
#pragma unroll
    for (int nt = 0; nt < 9; nt++)
#pragma unroll
        for (int i = 0; i < 4; i++) co[nt][i] = 0.f;

    unsigned hi = (unsigned)(lane >> 4);
    unsigned offQ = (unsigned)((warp*16 + (lane & 15))*QKS_H*2) + hi*16;
    unsigned offP = (unsigned)((warp*16 + (lane & 15))*PVS_H*2) + hi*16;
    unsigned offK[4], offV[4];
#pragma unroll
    for (int p = 0; p < 4; p++) {
        offK[p] = (unsigned)((p*16 + (lane & 15))*QKS_H*2) + hi*16;
        offV[p] = (unsigned)((p*16 + (lane & 15))*PVS_H*2) + hi*16;
    }
    unsigned offV8 = (unsigned)((64 + (lane & 7))*PVS_H*2) + ((unsigned)((lane >> 3) & 1))*16;

    const float scale = 0.11785113019775793f;
    const int NIT = S_TOK/AK2;

    for (int it = 0; it < NIT; it++) {
        int j0 = it*AK2;
        int b0 = it & 1, b1 = b0 ^ 1;
        __syncthreads();
        if (it + 1 < NIT) stageKV(j0 + AK2, b1);
        if (tid < 64) segk[tid] = seg_of(j0 + tid, soffs);
        CP_COMMIT;
        CP_WAIT1;
        __syncthreads();

        unsigned uKb = uK + (unsigned)b0*KBUF_H*2;
        unsigned uVb = uV + (unsigned)b0*VBUF_H*2;

        float sc[8][4];
#pragma unroll
        for (int nt = 0; nt < 8; nt++)
#pragma unroll
            for (int i = 0; i < 4; i++) sc[nt][i] = 0.f;
#pragma unroll
        for (int s = 0; s < 5; s++) {
            unsigned a[4], b[4][4];
            LDSM_X4(a, uQ + offQ + s*32);
#pragma unroll
            for (int p = 0; p < 4; p++) LDSM_X4(b[p], uKb + offK[p] + s*32);
#pragma unroll
            for (int p = 0; p < 4; p++) {
                MMA_F16(sc[2*p],   a, b[p][0], b[p][2]);
                MMA_F16(sc[2*p+1], a, b[p][1], b[p][3]);
            }
        }
        float mx1 = -1e30f, mx2 = -1e30f;
#pragma unroll
        for (int nt = 0; nt < 8; nt++) {
            int col = nt*8 + tg*2;
            int k0s = segk[col], k1s = segk[col+1];
            sc[nt][0] = sc[nt][0]*scale + (sq1 == k0s ? 1.f : 0.f);
            sc[nt][1] = sc[nt][1]*scale + (sq1 == k1s ? 1.f : 0.f);
            sc[nt][2] = sc[nt][2]*scale + (sq2 == k0s ? 1.f : 0.f);
            sc[nt][3] = sc[nt][3]*scale + (sq2 == k1s ? 1.f : 0.f);
            mx1 = fmaxf(mx1, fmaxf(sc[nt][0], sc[nt][1]));
            mx2 = fmaxf(mx2, fmaxf(sc[nt][2], sc[nt][3]));
        }
        mx1 = fmaxf(mx1, __shfl_xor_sync(0xffffffffu, mx1, 1, 4));
        mx1 = fmaxf(mx1, __shfl_xor_sync(0xffffffffu, mx1, 2, 4));
        mx2 = fmaxf(mx2, __shfl_xor_sync(0xffffffffu, mx2, 1, 4));
        mx2 = fmaxf(mx2, __shfl_xor_sync(0xffffffffu, mx2, 2, 4));
        float mn1 = fmaxf(m1, mx1), mn2 = fmaxf(m2, mx2);
        float f1 = __expf(m1 - mn1), f2 = __expf(m2 - mn2);
        m1 = mn1; m2 = mn2;
        float s1 = 0.f, s2 = 0.f;
#pragma unroll
        for (int nt = 0; nt < 8; nt++) {
            float p0 = __expf(sc[nt][0] - m1);
            float p1 = __expf(sc[nt][1] - m1);
            float p2 = __expf(sc[nt][2] - m2);
            float p3 = __expf(sc[nt][3] - m2);
            s1 += p0 + p1; s2 += p2 + p3;
            int col = nt*8 + tg*2;
            *(__half2*)&Ph[r1*PVS_H + col] = __floats2half2_rn(p0, p1);
            *(__half2*)&Ph[r2*PVS_H + col] = __floats2half2_rn(p2, p3);
        }
        s1 += __shfl_xor_sync(0xffffffffu, s1, 1, 4);
        s1 += __shfl_xor_sync(0xffffffffu, s1, 2, 4);
        s2 += __shfl_xor_sync(0xffffffffu, s2, 1, 4);
        s2 += __shfl_xor_sync(0xffffffffu, s2, 2, 4);
        l1 = l1*f1 + s1; l2 = l2*f2 + s2;
#pragma unroll
        for (int nt = 0; nt < 9; nt++) {
            co[nt][0] *= f1; co[nt][1] *= f1;
            co[nt][2] *= f2; co[nt][3] *= f2;
        }
        __syncthreads();
#pragma unroll
        for (int s = 0; s < 4; s++) {
            unsigned a[4], b[4][4], b8[2];
            LDSM_X4(a, uP + offP + s*32);
#pragma unroll
            for (int p = 0; p < 4; p++) LDSM_X4(b[p], uVb + offV[p] + s*32);
            LDSM_X2(b8, uVb + offV8 + s*32);
#pragma unroll
            for (int p = 0; p < 4; p++) {
                MMA_F16(co[2*p],   a, b[p][0], b[p][2]);
                MMA_F16(co[2*p+1], a, b[p][1], b[p][3]);
            }
            MMA_F16(co[8], a, b8[0], b8[1]);
        }
    }

    float i1 = 1.f/l1, i2 = 1.f/l2;
#pragma unroll
    for (int nt = 0; nt < 9; nt++) {
        int d0 = nt*8 + tg*2;
        *(__half2*)&out[(size_t)(q0+r1)*HID + h*HD + d0] =
            __floats2half2_rn(co[nt][0]*i1, co[nt][1]*i1);
        *(__half2*)&out[(size_t)(q0+r2)*HID + h*HD + d0] =
            __floats2half2_rn(co[nt][2]*i2, co[nt][3]*i2);
    }
}

// ---------------- launch ----------------
extern "C" void kernel_launch(void* const* d_in, const int* in_sizes, int n_in,
                              void* d_out, int out_size) {
    const float* x      = (const float*)d_in[0];
    const int*   offs   = (const int*)  d_in[1];
    const float* fc     = (const float*)d_in[2];
    const float* ln0_g  = (const float*)d_in[3];
    const float* ln0_b  = (const float*)d_in[4];
    const float* wqkv_w = (const float*)d_in[5];
    const float* wqkv_b = (const float*)d_in[6];
    const float* wo_w   = (const float*)d_in[7];
    const float* wo_b   = (const float*)d_in[8];
    const float* ln1_g  = (const float*)d_in[9];
    const float* ln1_b  = (const float*)d_in[10];
    const float* w1     = (const float*)d_in[11];
    const float* b1     = (const float*)d_in[12];
    const float* w2     = (const float*)d_in[13];
    const float* b2     = (const float*)d_in[14];
    float* out = (float*)d_out;

    float *x2;
    __half *qkvh, *Qr, *Kr, *Vt, *h0h, *attnh, *h1h, *mlph;
    __half *wqkvth, *woth, *w1th, *w2th;
    cudaGetSymbolAddress((void**)&x2,     g_x2);
    cudaGetSymbolAddress((void**)&qkvh,   g_qkvh);
    cudaGetSymbolAddress((void**)&Qr,     g_Qr);
    cudaGetSymbolAddress((void**)&Kr,     g_Kr);
    cudaGetSymbolAddress((void**)&Vt,     g_Vt);
    cudaGetSymbolAddress((void**)&h0h,    g_h0h);
    cudaGetSymbolAddress((void**)&attnh,  g_attnh);
    cudaGetSymbolAddress((void**)&h1h,    g_h1h);
    cudaGetSymbolAddress((void**)&mlph,   g_mlph);
    cudaGetSymbolAddress((void**)&wqkvth, g_wqkvth);
    cudaGetSymbolAddress((void**)&woth,   g_woth);
    cudaGetSymbolAddress((void**)&w1th,   g_w1th);
    cudaGetSymbolAddress((void**)&w2th,   g_w2th);

    cudaFuncSetAttribute(hgemm, cudaFuncAttributeMaxDynamicSharedMemorySize, GEMM_SMEM);
    cudaFuncSetAttribute(hgemm64, cudaFuncAttributeMaxDynamicSharedMemorySize, GEMM64_SMEM);
    cudaFuncSetAttribute(attn2_kernel, cudaFuncAttributeMaxDynamicSharedMemorySize, ATTN_SMEM);

    // 0. fused weight transposes -> [N][K] fp16
    transpose_all<<<TG_ALL, dim3(32,8)>>>(wqkv_w, wqkvth, wo_w, woth, w1, w1th, w2, w2th);

    // 1. LN0 -> fp16
    ln_kernel<<<S_TOK, 256>>>(x, ln0_g, ln0_b, h0h);
    // 2. QKV = h0 @ wqkv + b  -> fp16
    hgemm<<<dim3(QKV_N/128, S_TOK/128), 256, GEMM_SMEM>>>(
        h0h, HID, wqkvth, HID, wqkv_b, nullptr, qkvh, QKV_N, QKV_N, HID/GBK, 3);
    // 3. rope prep
    rope_prep<<<dim3(S_TOK/128, NH), 256>>>(qkvh, fc, Qr, Kr, Vt);
    // 4. attention -> fp16
    attn2_kernel<<<dim3(S_TOK/AQ2, NH), 256, ATTN_SMEM>>>(Qr, Kr, Vt, offs, attnh);
    // 5. x2 = x + attn @ wo + b  (64-row tiles: better wave fill at N=1152)
    hgemm64<<<dim3(HID/128, S_TOK/64), 256, GEMM64_SMEM>>>(
        attnh, HID, woth, HID, wo_b, x, x2, HID, HID, HID/GBK, 1);
    // 6. LN1 -> fp16
    ln_kernel<<<S_TOK, 256>>>(x2, ln1_g, ln1_b, h1h);
    // 7. mlp = gelu(h1 @ w1 + b1) -> fp16
    hgemm<<<dim3((MLP_DIM+127)/128, S_TOK/128), 256, GEMM_SMEM>>>(
        h1h, HID, w1th, HID, b1, nullptr, mlph, MLP_P2, MLP_DIM, HID/GBK, 2);
    // 8. out = x2 + mlp @ w2 + b2  (64-row tiles)
    hgemm64<<<dim3(HID/128, S_TOK/64), 256, GEMM64_SMEM>>>(
        mlph, MLP_P2, w2th, MLP_P2, b2, x2, out, HID, HID, MLP_P2/GBK, 1);
}

// round 16
// speedup vs baseline: 1.4918x; 1.4918x over previous
#include <cuda_runtime.h>
#include <cuda_bf16.h>
#include <cuda_fp16.h>
#include <stdint.h>
#include <math.h>

// Problem constants
#define S_TOK 3072
#define HID 1152
#define NH 16
#define HD 72
#define MLP_DIM 4304
#define MLP_P2 4352           // MLP_DIM padded to multiple of 64 (zeros in pad)
#define QKV_N (3*HID)         // 3456
#define EPS 1e-5f

// ---------------- scratch (allocation-free: __device__ globals, zero-init) ----
__device__ float g_x2[S_TOK*HID];
__device__ unsigned short g_qkvh[S_TOK*QKV_N];
__device__ unsigned short g_Qr[NH*S_TOK*80];
__device__ unsigned short g_Kr[NH*S_TOK*80];
__device__ unsigned short g_Vt[NH*HD*S_TOK];
__device__ unsigned short g_h0h[S_TOK*HID];
__device__ unsigned short g_attnh[S_TOK*HID];
__device__ unsigned short g_h1h[S_TOK*HID];
__device__ unsigned short g_mlph[S_TOK*MLP_P2];
__device__ unsigned short g_wqkvth[QKV_N*HID];
__device__ unsigned short g_woth[HID*HID];
__device__ unsigned short g_w1th[MLP_DIM*HID];
__device__ unsigned short g_w2th[HID*MLP_P2];

// ---------------- PTX helpers ----------------
__device__ __forceinline__ uint32_t smem_u32(const void* p) {
    uint32_t a;
    asm("{ .reg .u64 t; cvta.to.shared.u64 t, %1; cvt.u32.u64 %0, t; }"
        : "=r"(a) : "l"(p));
    return a;
}

#define MMA_F16(C, A, B0, B1)                                               \
    asm volatile("mma.sync.aligned.m16n8k16.row.col.f32.f16.f16.f32 "       \
                 "{%0,%1,%2,%3}, {%4,%5,%6,%7}, {%8,%9}, {%0,%1,%2,%3};\n"  \
                 : "+f"((C)[0]), "+f"((C)[1]), "+f"((C)[2]), "+f"((C)[3])   \
                 : "r"((A)[0]), "r"((A)[1]), "r"((A)[2]), "r"((A)[3]),      \
                   "r"(B0), "r"(B1))

#define LDSM_X4(R, a)                                                          \
    asm volatile("ldmatrix.sync.aligned.m8n8.x4.shared.b16 {%0,%1,%2,%3}, [%4];" \
                 : "=r"((R)[0]), "=r"((R)[1]), "=r"((R)[2]), "=r"((R)[3])      \
                 : "r"(a))
#define LDSM_X2(R, a)                                                          \
    asm volatile("ldmatrix.sync.aligned.m8n8.x2.shared.b16 {%0,%1}, [%2];"     \
                 : "=r"((R)[0]), "=r"((R)[1]) : "r"(a))

__device__ __forceinline__ void cp_async16(unsigned dst, const void* src, bool valid) {
    int sz = valid ? 16 : 0;
    asm volatile("cp.async.cg.shared.global [%0], [%1], 16, %2;"
                 :: "r"(dst), "l"(src), "r"(sz));
}
#define CP_COMMIT asm volatile("cp.async.commit_group;")
#define CP_WAIT1  asm volatile("cp.async.wait_group 1;")

__device__ __forceinline__ float gelu_fast(float v) {
    float u = 0.7978845608028654f * (v + 0.044715f * v * v * v);
    return v / (1.0f + __expf(-2.0f * u));
}

// ---------------- LayerNorm (warp-shuffle reduce, fp16 out) -----------------
__global__ void ln_kernel(const float* __restrict__ x, const float* __restrict__ g,
                          const float* __restrict__ b, __half* __restrict__ y) {
    __shared__ float row[HID];
    __shared__ float ws[8], wss[8], bc[2];
    int r = blockIdx.x;
    int tid = threadIdx.x, lane = tid & 31, warp = tid >> 5;
    float s = 0.f, ss = 0.f;
    for (int i = tid; i < HID; i += 256) {
        float v = x[(size_t)r*HID + i];
        row[i] = v;
        s += v; ss += v*v;
    }
#pragma unroll
    for (int o = 16; o > 0; o >>= 1) {
        s  += __shfl_xor_sync(0xffffffffu, s, o);
        ss += __shfl_xor_sync(0xffffffffu, ss, o);
    }
    if (lane == 0) { ws[warp] = s; wss[warp] = ss; }
    __syncthreads();
    if (warp == 0) {
        float a = (lane < 8) ? ws[lane] : 0.f;
        float c = (lane < 8) ? wss[lane] : 0.f;
#pragma unroll
        for (int o = 4; o > 0; o >>= 1) {
            a += __shfl_xor_sync(0xffffffffu, a, o, 8);
            c += __shfl_xor_sync(0xffffffffu, c, o, 8);
        }
        if (lane == 0) {
            float mu = a * (1.0f/HID);
            float var = c * (1.0f/HID) - mu*mu;
            bc[0] = mu; bc[1] = rsqrtf(var + EPS);
        }
    }
    __syncthreads();
    float mu = bc[0], rstd = bc[1];
    for (int i = tid; i < HID; i += 256) {
        y[(size_t)r*HID + i] = __float2half_rn((row[i] - mu) * rstd * g[i] + b[i]);
    }
}

// ---------------- fused transpose of all 4 weights ([K][N]->[N][K], fp16) ----
#define TG0 (108*36)         // wqkv: N=3456 -> 108 x-tiles, K=1152 -> 36 y
#define TG1 (36*36)          // wo
#define TG2 (135*36)         // w1: N=4304 -> 135, K=1152
#define TG3 (36*135)         // w2: N=1152 -> 36, K=4304 -> 135
#define TG_ALL (TG0+TG1+TG2+TG3)

__global__ void transpose_all(const float* __restrict__ i0, __half* __restrict__ o0,
                              const float* __restrict__ i1, __half* __restrict__ o1,
                              const float* __restrict__ i2, __half* __restrict__ o2,
                              const float* __restrict__ i3, __half* __restrict__ o3) {
    __shared__ float t[32][33];
    int id = blockIdx.x;
    const float* in; __half* out; int K, N, out_ld, nx;
    if (id < TG0)            { in=i0; out=o0; K=HID;     N=QKV_N;   out_ld=HID;    nx=108; }
    else if (id < TG0+TG1)   { id-=TG0;         in=i1; out=o1; K=HID;     N=HID;     out_ld=HID;    nx=36; }
    else if (id < TG0+TG1+TG2){ id-=TG0+TG1;    in=i2; out=o2; K=HID;     N=MLP_DIM; out_ld=HID;    nx=135; }
    else                     { id-=TG0+TG1+TG2; in=i3; out=o3; K=MLP_DIM; N=HID;     out_ld=MLP_P2; nx=36; }
    int kb = (id/nx)*32, nb = (id%nx)*32;
    int x = threadIdx.x, y = threadIdx.y;   // 32 x 8
#pragma unroll
    for (int i = 0; i < 32; i += 8) {
        int k = kb + y + i, n = nb + x;
        t[y+i][x] = (k < K && n < N) ? in[(size_t)k*N + n] : 0.f;
    }
    __syncthreads();
#pragma unroll
    for (int i = 0; i < 32; i += 8) {
        int n = nb + y + i, k = kb + x;
        if (n < N && k < K) out[(size_t)n*out_ld + k] = __float2half_rn(t[x][y+i]);
    }
}

// ---------------- rope prep: qkvh -> Qr/Kr (rope'd, [h][tok][80]) + Vt ------
#define VS_P 82
__global__ void rope_prep(const __half* __restrict__ qkv, const float* __restrict__ fc,
                          __half* __restrict__ Qr, __half* __restrict__ Kr,
                          __half* __restrict__ Vt) {
    __shared__ __half vs[128*VS_P];
    int tid = threadIdx.x;
    int h = blockIdx.y, t0 = blockIdx.x*128;

    for (int t = tid; t < 128*9; t += 256) {
        int row = t/9, ch = t - row*9;
        int tok = t0 + row, d0 = ch*8;
        float4 cA = *(const float4*)&fc[(size_t)tok*HD + d0];
        float4 cB = *(const float4*)&fc[(size_t)tok*HD + d0 + 4];
        {
            uint4 raw = *(const uint4*)&qkv[(size_t)tok*QKV_N + h*HD + d0];
            float2 f0 = __half22float2(*(__half2*)&raw.x);
            float2 f1 = __half22float2(*(__half2*)&raw.y);
            float2 f2 = __half22float2(*(__half2*)&raw.z);
            float2 f3 = __half22float2(*(__half2*)&raw.w);
            uint4 o;
            *(__half2*)&o.x = __floats2half2_rn(f0.x*cA.x - f0.y*cA.y, f0.x*cA.y + f0.y*cA.x);
            *(__half2*)&o.y = __floats2half2_rn(f1.x*cA.z - f1.y*cA.w, f1.x*cA.w + f1.y*cA.z);
            *(__half2*)&o.z = __floats2half2_rn(f2.x*cB.x - f2.y*cB.y, f2.x*cB.y + f2.y*cB.x);
            *(__half2*)&o.w = __floats2half2_rn(f3.x*cB.z - f3.y*cB.w, f3.x*cB.w + f3.y*cB.z);
            *(uint4*)&Qr[((size_t)h*S_TOK + tok)*80 + d0] = o;
        }
        {
            uint4 raw = *(const uint4*)&qkv[(size_t)tok*QKV_N + HID + h*HD + d0];
            float2 f0 = __half22float2(*(__half2*)&raw.x);
            float2 f1 = __half22float2(*(__half2*)&raw.y);
            float2 f2 = __half22float2(*(__half2*)&raw.z);
            float2 f3 = __half22float2(*(__half2*)&raw.w);
            uint4 o;
            *(__half2*)&o.x = __floats2half2_rn(f0.x*cA.x - f0.y*cA.y, f0.x*cA.y + f0.y*cA.x);
            *(__half2*)&o.y = __floats2half2_rn(f1.x*cA.z - f1.y*cA.w, f1.x*cA.w + f1.y*cA.z);
            *(__half2*)&o.z = __floats2half2_rn(f2.x*cB.x - f2.y*cB.y, f2.x*cB.y + f2.y*cB.x);
            *(__half2*)&o.w = __floats2half2_rn(f3.x*cB.z - f3.y*cB.w, f3.x*cB.w + f3.y*cB.z);
            *(uint4*)&Kr[((size_t)h*S_TOK + tok)*80 + d0] = o;
        }
    }
    if (tid < 128) {
        int tok = t0 + tid;
        *(uint4*)&Qr[((size_t)h*S_TOK + tok)*80 + 72] = make_uint4(0,0,0,0);
        *(uint4*)&Kr[((size_t)h*S_TOK + tok)*80 + 72] = make_uint4(0,0,0,0);
    }
    for (int t = tid; t < 128*9; t += 256) {
        int row = t/9, ch = t - row*9;
        int d0 = ch*8;
        uint4 raw = *(const uint4*)&qkv[(size_t)(t0+row)*QKV_N + 2*HID + h*HD + d0];
        uint32_t* w = (uint32_t*)&vs[row*VS_P + d0];
        w[0] = raw.x; w[1] = raw.y; w[2] = raw.z; w[3] = raw.w;
    }
    __syncthreads();
    for (int t = tid; t < HD*16; t += 256) {
        int d = t >> 4, cg = t & 15;
        int tok = cg*8;
        __half tmp[8];
#pragma unroll
        for (int i = 0; i < 8; i++) tmp[i] = vs[(tok+i)*VS_P + d];
        *(uint4*)&Vt[((size_t)h*HD + d)*S_TOK + t0 + tok] = *(uint4*)tmp;
    }
}

// ---------------- fp16 GEMM 128x128, 3-stage cp.async (all GEMMs) -----------
#define GBK 64
#define TILE_B (128*128)
#define STAGE_B (2*TILE_B)
#define NSTAGE 3
#define GEMM_SMEM (NSTAGE*STAGE_B)   // 98304

__global__ void __launch_bounds__(256, 2)
hgemm(const __half* __restrict__ A, int ldA,
      const __half* __restrict__ Bt, int ldB,
      const float* __restrict__ bias, const float* __restrict__ residual,
      void* __restrict__ Cv, int ldC, int N, int NIT, int mode) {
    extern __shared__ char smg[];
    unsigned sbase = smem_u32(smg);
    int tid = threadIdx.x, warp = tid >> 5, lane = tid & 31;
    int g = lane >> 2, tg = lane & 3;
    int wy = warp >> 1, wx = warp & 1;
    int m0 = blockIdx.y*128, n0 = blockIdx.x*128;

    float c[2][8][4];
#pragma unroll
    for (int mt = 0; mt < 2; mt++)
#pragma unroll
        for (int nt = 0; nt < 8; nt++)
#pragma unroll
            for (int i = 0; i < 4; i++) c[mt][nt][i] = 0.f;

    auto stage = [&](int it, int buf) {
        int k0 = it*GBK;
        unsigned sA = sbase + buf*STAGE_B;
        unsigned sB = sA + TILE_B;
#pragma unroll
        for (int i = 0; i < 4; i++) {
            int t = tid + i*256;
            int row = t >> 3, ch = t & 7;
            unsigned off = (unsigned)(row*128) + ((unsigned)(ch ^ (row & 7)) << 4);
            cp_async16(sA + off, A + (size_t)(m0+row)*ldA + k0 + ch*8, true);
            int n = n0 + row;
            bool v = (n < N);
            cp_async16(sB + off, Bt + (size_t)(v ? n : 0)*ldB + k0 + ch*8, v);
        }
    };

    stage(0, 0); CP_COMMIT;
    if (NIT > 1) stage(1, 1);
    CP_COMMIT;

    unsigned hi = (unsigned)(lane >> 4);
    unsigned aoff[2], amask[2], boff[4], bmask[4];
#pragma unroll
    for (int mt = 0; mt < 2; mt++) {
        int r = wy*32 + mt*16 + (lane & 15);
        aoff[mt] = (unsigned)(r*128); amask[mt] = (unsigned)(r & 7);
    }
#pragma unroll
    for (int p = 0; p < 4; p++) {
        int r = wx*64 + p*16 + (lane & 15);
        boff[p] = (unsigned)(r*128); bmask[p] = (unsigned)(r & 7);
    }

    for (int it = 0; it < NIT; it++) {
        CP_WAIT1;
        __syncthreads();
        if (it + 2 < NIT) stage(it+2, (it+2)%NSTAGE);
        CP_COMMIT;
        unsigned sA = sbase + (it%NSTAGE)*STAGE_B;
        unsigned sB = sA + TILE_B;
#pragma unroll
        for (int s = 0; s < 4; s++) {
            unsigned ci = (unsigned)(s*2) + hi;
            unsigned a[2][4], b[4][4];
#pragma unroll
            for (int mt = 0; mt < 2; mt++)
                LDSM_X4(a[mt], sA + aoff[mt] + ((ci ^ amask[mt]) << 4));
#pragma unroll
            for (int p = 0; p < 4; p++)
                LDSM_X4(b[p], sB + boff[p] + ((ci ^ bmask[p]) << 4));
#pragma unroll
            for (int mt = 0; mt < 2; mt++)
#pragma unroll
                for (int p = 0; p < 4; p++) {
                    MMA_F16(c[mt][2*p],   a[mt], b[p][0], b[p][2]);
                    MMA_F16(c[mt][2*p+1], a[mt], b[p][1], b[p][3]);
                }
        }
    }

    float* Cf = (float*)Cv;
    __half* Ch = (__half*)Cv;
#pragma unroll
    for (int mt = 0; mt < 2; mt++) {
        int row0 = m0 + wy*32 + mt*16 + g;
#pragma unroll
        for (int nt = 0; nt < 8; nt++) {
            int col = n0 + wx*64 + nt*8 + tg*2;
            if (col >= N) continue;
#pragma unroll
            for (int hf = 0; hf < 2; hf++) {
                int r = row0 + hf*8;
                float v0 = c[mt][nt][hf*2+0] + bias[col];
                float v1 = c[mt][nt][hf*2+1] + bias[col+1];
                if (mode == 1) {
                    v0 += residual[(size_t)r*ldC + col];
                    v1 += residual[(size_t)r*ldC + col + 1];
                    *(float2*)&Cf[(size_t)r*ldC + col] = make_float2(v0, v1);
                } else if (mode == 2) {
                    *(__half2*)&Ch[(size_t)r*ldC + col] =
                        __floats2half2_rn(gelu_fast(v0), gelu_fast(v1));
                } else if (mode == 3) {
                    *(__half2*)&Ch[(size_t)r*ldC + col] = __floats2half2_rn(v0, v1);
                } else {
                    *(float2*)&Cf[(size_t)r*ldC + col] = make_float2(v0, v1);
                }
            }
        }
    }
}

// ---------------- attention: double-buffered K/V prefetch -------------------
#define AQ2 128
#define AK2 64
#define QKS_H 88
#define PVS_H 72
#define KBUF_H (AK2*QKS_H)
#define VBUF_H (HD*PVS_H)

__device__ __forceinline__ int seg_of(int t, const int* offs) {
    int s = 0;
#pragma unroll
    for (int i = 1; i <= 6; i++) if (offs[i] <= t) s = i;
    return s;
}

#define ATTN_SMEM ((AQ2*QKS_H + 2*KBUF_H + 2*VBUF_H + AQ2*PVS_H)*2 + (64+8)*4)

__global__ void __launch_bounds__(256)
attn2_kernel(const __half* __restrict__ Qr, const __half* __restrict__ Kr,
             const __half* __restrict__ Vt, const int* __restrict__ offs,
             __half* __restrict__ out) {
    extern __shared__ char sm[];
    __half* Qh = (__half*)sm;
    __half* Ph = Qh + AQ2*QKS_H + 2*KBUF_H + 2*VBUF_H;
    int* segk  = (int*)(Ph + AQ2*PVS_H);
    int* soffs = segk + 64;

    unsigned sbase = smem_u32(sm);
    unsigned uQ = sbase;
    unsigned uK = uQ + AQ2*QKS_H*2;
    unsigned uV = uK + 2*KBUF_H*2;
    unsigned uP = uV + 2*VBUF_H*2;

    int tid = threadIdx.x, warp = tid >> 5, lane = tid & 31;
    int g = lane >> 2, tg = lane & 3;
    int h = blockIdx.y, q0 = blockIdx.x*AQ2;

    if (tid < 7) soffs[tid] = offs[tid];

    auto stageKV = [&](int j0, int buf) {
        const __half* ksrc = Kr + ((size_t)h*S_TOK + j0)*80;
        unsigned kd = uK + (unsigned)buf*KBUF_H*2;
        for (int t = tid; t < AK2*10; t += 256) {
            int row = t/10, ch = t - row*10;
            cp_async16(kd + (unsigned)(row*QKS_H*2 + ch*16), ksrc + row*80 + ch*8, true);
        }
        const __half* vsrc = Vt + (size_t)h*HD*S_TOK + j0;
        unsigned vd = uV + (unsigned)buf*VBUF_H*2;
        for (int t = tid; t < HD*8; t += 256) {
            int d = t >> 3, cg = t & 7;
            cp_async16(vd + (unsigned)(d*PVS_H*2 + cg*16), vsrc + (size_t)d*S_TOK + cg*8, true);
        }
    };

    {
        const __half* qsrc = Qr + ((size_t)h*S_TOK + q0)*80;
        for (int t = tid; t < AQ2*10; t += 256) {
            int row = t/10, ch = t - row*10;
            cp_async16(uQ + (unsigned)(row*QKS_H*2 + ch*16), qsrc + row*80 + ch*8, true);
        }
        stageKV(0, 0);
        CP_COMMIT;
    }
    __syncthreads();

    int r1 = warp*16 + g, r2 = r1 + 8;
    int sq1 = seg_of(q0 + r1, soffs);
    int sq2 = seg_of(q0 + r2, soffs);

    float m1 = -1e30f, m2 = -1e30f, l1 = 0.f, l2 = 0.f;
    float co[9][4];
#pragma unroll
    for (int nt = 0; nt < 9; nt++)
#pragma unroll
        for (int i = 0; i < 4; i++) co[nt][i] = 0.f;

    unsigned hi = (unsigned)(lane >> 4);
    unsigned offQ = (unsigned)((warp*16 + (lane & 15))*QKS_H*2) + hi*16;
    unsigned offP = (unsigned)((warp*16 + (lane & 15))*PVS_H*2) + hi*16;
    unsigned offK[4], offV[4];
#pragma unroll
    for (int p = 0; p < 4; p++) {
        offK[p] = (unsigned)((p*16 + (lane & 15))*QKS_H*2) + hi*16;
        offV[p] = (unsigned)((p*16 + (lane & 15))*PVS_H*2) + hi*16;
    }
    unsigned offV8 = (unsigned)((64 + (lane & 7))*PVS_H*2) + ((unsigned)((lane >> 3) & 1))*16;

    const float scale = 0.11785113019775793f;
    const int NIT = S_TOK/AK2;

    for (int it = 0; it < NIT; it++) {
        int j0 = it*AK2;
        int b0 = it & 1, b1 = b0 ^ 1;
        __syncthreads();
        if (it + 1 < NIT) stageKV(j0 + AK2, b1);
        if (tid < 64) segk[tid] = seg_of(j0 + tid, soffs);
        CP_COMMIT;
        CP_WAIT1;
        __syncthreads();

        unsigned uKb = uK + (unsigned)b0*KBUF_H*2;
        unsigned uVb = uV + (unsigned)b0*VBUF_H*2;

        float sc[8][4];
#pragma unroll
        for (int nt = 0; nt < 8; nt++)
#pragma unroll
            for (int i = 0; i < 4; i++) sc[nt][i] = 0.f;
#pragma unroll
        for (int s = 0; s < 5; s++) {
            unsigned a[4], b[4][4];
            LDSM_X4(a, uQ + offQ + s*32);
#pragma unroll
            for (int p = 0; p < 4; p++) LDSM_X4(b[p], uKb + offK[p] + s*32);
#pragma unroll
            for (int p = 0; p < 4; p++) {
                MMA_F16(sc[2*p],   a, b[p][0], b[p][2]);
                MMA_F16(sc[2*p+1], a, b[p][1], b[p][3]);
            }
        }
        float mx1 = -1e30f, mx2 = -1e30f;
#pragma unroll
        for (int nt = 0; nt < 8; nt++) {
            int col = nt*8 + tg*2;
            int k0s = segk[col], k1s = segk[col+1];
            sc[nt][0] = sc[nt][0]*scale + (sq1 == k0s ? 1.f : 0.f);
            sc[nt][1] = sc[nt][1]*scale + (sq1 == k1s ? 1.f : 0.f);
            sc[nt][2] = sc[nt][2]*scale + (sq2 == k0s ? 1.f : 0.f);
            sc[nt][3] = sc[nt][3]*scale + (sq2 == k1s ? 1.f : 0.f);
            mx1 = fmaxf(mx1, fmaxf(sc[nt][0], sc[nt][1]));
            mx2 = fmaxf(mx2, fmaxf(sc[nt][2], sc[nt][3]));
        }
        mx1 = fmaxf(mx1, __shfl_xor_sync(0xffffffffu, mx1, 1, 4));
        mx1 = fmaxf(mx1, __shfl_xor_sync(0xffffffffu, mx1, 2, 4));
        mx2 = fmaxf(mx2, __shfl_xor_sync(0xffffffffu, mx2, 1, 4));
        mx2 = fmaxf(mx2, __shfl_xor_sync(0xffffffffu, mx2, 2, 4));
        float mn1 = fmaxf(m1, mx1), mn2 = fmaxf(m2, mx2);
        float f1 = __expf(m1 - mn1), f2 = __expf(m2 - mn2);
        m1 = mn1; m2 = mn2;
        float s1 = 0.f, s2 = 0.f;
#pragma unroll
        for (int nt = 0; nt < 8; nt++) {
            float p0 = __expf(sc[nt][0] - m1);
            float p1 = __expf(sc[nt][1] - m1);
            float p2 = __expf(sc[nt][2] - m2);
            float p3 = __expf(sc[nt][3] - m2);
            s1 += p0 + p1; s2 += p2 + p3;
            int col = nt*8 + tg*2;
            *(__half2*)&Ph[r1*PVS_H + col] = __floats2half2_rn(p0, p1);
            *(__half2*)&Ph[r2*PVS_H + col] = __floats2half2_rn(p2, p3);
        }
        s1 += __shfl_xor_sync(0xffffffffu, s1, 1, 4);
        s1 += __shfl_xor_sync(0xffffffffu, s1, 2, 4);
        s2 += __shfl_xor_sync(0xffffffffu, s2, 1, 4);
        s2 += __shfl_xor_sync(0xffffffffu, s2, 2, 4);
        l1 = l1*f1 + s1; l2 = l2*f2 + s2;
#pragma unroll
        for (int nt = 0; nt < 9; nt++) {
            co[nt][0] *= f1; co[nt][1] *= f1;
            co[nt][2] *= f2; co[nt][3] *= f2;
        }
        __syncthreads();
#pragma unroll
        for (int s = 0; s < 4; s++) {
            unsigned a[4], b[4][4], b8[2];
            LDSM_X4(a, uP + offP + s*32);
#pragma unroll
            for (int p = 0; p < 4; p++) LDSM_X4(b[p], uVb + offV[p] + s*32);
            LDSM_X2(b8, uVb + offV8 + s*32);
#pragma unroll
            for (int p = 0; p < 4; p++) {
                MMA_F16(co[2*p],   a, b[p][0], b[p][2]);
                MMA_F16(co[2*p+1], a, b[p][1], b[p][3]);
            }
            MMA_F16(co[8], a, b8[0], b8[1]);
        }
    }

    float i1 = 1.f/l1, i2 = 1.f/l2;
#pragma unroll
    for (int nt = 0; nt < 9; nt++) {
        int d0 = nt*8 + tg*2;
        *(__half2*)&out[(size_t)(q0+r1)*HID + h*HD + d0] =
            __floats2half2_rn(co[nt][0]*i1, co[nt][1]*i1);
        *(__half2*)&out[(size_t)(q0+r2)*HID + h*HD + d0] =
            __floats2half2_rn(co[nt][2]*i2, co[nt][3]*i2);
    }
}

// ---------------- launch ----------------
extern "C" void kernel_launch(void* const* d_in, const int* in_sizes, int n_in,
                              void* d_out, int out_size) {
    const float* x      = (const float*)d_in[0];
    const int*   offs   = (const int*)  d_in[1];
    const float* fc     = (const float*)d_in[2];
    const float* ln0_g  = (const float*)d_in[3];
    const float* ln0_b  = (const float*)d_in[4];
    const float* wqkv_w = (const float*)d_in[5];
    const float* wqkv_b = (const float*)d_in[6];
    const float* wo_w   = (const float*)d_in[7];
    const float* wo_b   = (const float*)d_in[8];
    const float* ln1_g  = (const float*)d_in[9];
    const float* ln1_b  = (const float*)d_in[10];
    const float* w1     = (const float*)d_in[11];
    const float* b1     = (const float*)d_in[12];
    const float* w2     = (const float*)d_in[13];
    const float* b2     = (const float*)d_in[14];
    float* out = (float*)d_out;

    float *x2;
    __half *qkvh, *Qr, *Kr, *Vt, *h0h, *attnh, *h1h, *mlph;
    __half *wqkvth, *woth, *w1th, *w2th;
    cudaGetSymbolAddress((void**)&x2,     g_x2);
    cudaGetSymbolAddress((void**)&qkvh,   g_qkvh);
    cudaGetSymbolAddress((void**)&Qr,     g_Qr);
    cudaGetSymbolAddress((void**)&Kr,     g_Kr);
    cudaGetSymbolAddress((void**)&Vt,     g_Vt);
    cudaGetSymbolAddress((void**)&h0h,    g_h0h);
    cudaGetSymbolAddress((void**)&attnh,  g_attnh);
    cudaGetSymbolAddress((void**)&h1h,    g_h1h);
    cudaGetSymbolAddress((void**)&mlph,   g_mlph);
    cudaGetSymbolAddress((void**)&wqkvth, g_wqkvth);
    cudaGetSymbolAddress((void**)&woth,   g_woth);
    cudaGetSymbolAddress((void**)&w1th,   g_w1th);
    cudaGetSymbolAddress((void**)&w2th,   g_w2th);

    cudaFuncSetAttribute(hgemm, cudaFuncAttributeMaxDynamicSharedMemorySize, GEMM_SMEM);
    cudaFuncSetAttribute(attn2_kernel, cudaFuncAttributeMaxDynamicSharedMemorySize, ATTN_SMEM);

    // 0. fused weight transposes -> [N][K] fp16
    transpose_all<<<TG_ALL, dim3(32,8)>>>(wqkv_w, wqkvth, wo_w, woth, w1, w1th, w2, w2th);

    // 1. LN0 -> fp16
    ln_kernel<<<S_TOK, 256>>>(x, ln0_g, ln0_b, h0h);
    // 2. QKV = h0 @ wqkv + b  -> fp16
    hgemm<<<dim3(QKV_N/128, S_TOK/128), 256, GEMM_SMEM>>>(
        h0h, HID, wqkvth, HID, wqkv_b, nullptr, qkvh, QKV_N, QKV_N, HID/GBK, 3);
    // 3. rope prep
    rope_prep<<<dim3(S_TOK/128, NH), 256>>>(qkvh, fc, Qr, Kr, Vt);
    // 4. attention -> fp16
    attn2_kernel<<<dim3(S_TOK/AQ2, NH), 256, ATTN_SMEM>>>(Qr, Kr, Vt, offs, attnh);
    // 5. x2 = x + attn @ wo + b  (fp32 out)
    hgemm<<<dim3(HID/128, S_TOK/128), 256, GEMM_SMEM>>>(
        attnh, HID, woth, HID, wo_b, x, x2, HID, HID, HID/GBK, 1);
    // 6. LN1 -> fp16
    ln_kernel<<<S_TOK, 256>>>(x2, ln1_g, ln1_b, h1h);
    // 7. mlp = gelu(h1 @ w1 + b1) -> fp16
    hgemm<<<dim3((MLP_DIM+127)/128, S_TOK/128), 256, GEMM_SMEM>>>(
        h1h, HID, w1th, HID, b1, nullptr, mlph, MLP_P2, MLP_DIM, HID/GBK, 2);
    // 8. out = x2 + mlp @ w2 + b2
    hgemm<<<dim3(HID/128, S_TOK/128), 256, GEMM_SMEM>>>(
        mlph, MLP_P2, w2th, MLP_P2, b2, x2, out, HID, HID, MLP_P2/GBK, 1);
}

// round 17
// speedup vs baseline: 1.4950x; 1.0021x over previous
#include <cuda_runtime.h>
#include <cuda_bf16.h>
#include <cuda_fp16.h>
#include <stdint.h>
#include <math.h>

// Problem constants
#define S_TOK 3072
#define HID 1152
#define NH 16
#define HD 72
#define MLP_DIM 4304
#define MLP_P2 4352           // MLP_DIM padded to multiple of 64 (zeros in pad)
#define QKV_N (3*HID)         // 3456
#define EPS 1e-5f

// ---------------- scratch (allocation-free: __device__ globals, zero-init) ----
__device__ float g_x2[S_TOK*HID];
__device__ unsigned short g_qkvh[S_TOK*QKV_N];      // only V section used
__device__ unsigned short g_Qr[NH*S_TOK*80];        // rope'd Q, [h][tok][80], pad zero
__device__ unsigned short g_Kr[NH*S_TOK*80];        // rope'd K, [h][tok][80], pad zero
__device__ unsigned short g_Vt[NH*HD*S_TOK];        // V^T, [h][d][tok]
__device__ unsigned short g_h0h[S_TOK*HID];
__device__ unsigned short g_attnh[S_TOK*HID];
__device__ unsigned short g_h1h[S_TOK*HID];
__device__ unsigned short g_mlph[S_TOK*MLP_P2];
__device__ unsigned short g_wqkvth[QKV_N*HID];
__device__ unsigned short g_woth[HID*HID];
__device__ unsigned short g_w1th[MLP_DIM*HID];
__device__ unsigned short g_w2th[HID*MLP_P2];

// ---------------- PTX helpers ----------------
__device__ __forceinline__ uint32_t smem_u32(const void* p) {
    uint32_t a;
    asm("{ .reg .u64 t; cvta.to.shared.u64 t, %1; cvt.u32.u64 %0, t; }"
        : "=r"(a) : "l"(p));
    return a;
}

#define MMA_F16(C, A, B0, B1)                                               \
    asm volatile("mma.sync.aligned.m16n8k16.row.col.f32.f16.f16.f32 "       \
                 "{%0,%1,%2,%3}, {%4,%5,%6,%7}, {%8,%9}, {%0,%1,%2,%3};\n"  \
                 : "+f"((C)[0]), "+f"((C)[1]), "+f"((C)[2]), "+f"((C)[3])   \
                 : "r"((A)[0]), "r"((A)[1]), "r"((A)[2]), "r"((A)[3]),      \
                   "r"(B0), "r"(B1))

#define LDSM_X4(R, a)                                                          \
    asm volatile("ldmatrix.sync.aligned.m8n8.x4.shared.b16 {%0,%1,%2,%3}, [%4];" \
                 : "=r"((R)[0]), "=r"((R)[1]), "=r"((R)[2]), "=r"((R)[3])      \
                 : "r"(a))
#define LDSM_X2(R, a)                                                          \
    asm volatile("ldmatrix.sync.aligned.m8n8.x2.shared.b16 {%0,%1}, [%2];"     \
                 : "=r"((R)[0]), "=r"((R)[1]) : "r"(a))

__device__ __forceinline__ void cp_async16(unsigned dst, const void* src, bool valid) {
    int sz = valid ? 16 : 0;
    asm volatile("cp.async.cg.shared.global [%0], [%1], 16, %2;"
                 :: "r"(dst), "l"(src), "r"(sz));
}
#define CP_COMMIT asm volatile("cp.async.commit_group;")
#define CP_WAIT1  asm volatile("cp.async.wait_group 1;")
#define CP_WAIT0  asm volatile("cp.async.wait_group 0;")

__device__ __forceinline__ float gelu_fast(float v) {
    float u = 0.7978845608028654f * (v + 0.044715f * v * v * v);
    return v / (1.0f + __expf(-2.0f * u));
}

// ---------------- LayerNorm (warp-shuffle reduce, fp16 out) -----------------
__global__ void ln_kernel(const float* __restrict__ x, const float* __restrict__ g,
                          const float* __restrict__ b, __half* __restrict__ y) {
    __shared__ float row[HID];
    __shared__ float ws[8], wss[8], bc[2];
    int r = blockIdx.x;
    int tid = threadIdx.x, lane = tid & 31, warp = tid >> 5;
    float s = 0.f, ss = 0.f;
    for (int i = tid; i < HID; i += 256) {
        float v = x[(size_t)r*HID + i];
        row[i] = v;
        s += v; ss += v*v;
    }
#pragma unroll
    for (int o = 16; o > 0; o >>= 1) {
        s  += __shfl_xor_sync(0xffffffffu, s, o);
        ss += __shfl_xor_sync(0xffffffffu, ss, o);
    }
    if (lane == 0) { ws[warp] = s; wss[warp] = ss; }
    __syncthreads();
    if (warp == 0) {
        float a = (lane < 8) ? ws[lane] : 0.f;
        float c = (lane < 8) ? wss[lane] : 0.f;
#pragma unroll
        for (int o = 4; o > 0; o >>= 1) {
            a += __shfl_xor_sync(0xffffffffu, a, o, 8);
            c += __shfl_xor_sync(0xffffffffu, c, o, 8);
        }
        if (lane == 0) {
            float mu = a * (1.0f/HID);
            float var = c * (1.0f/HID) - mu*mu;
            bc[0] = mu; bc[1] = rsqrtf(var + EPS);
        }
    }
    __syncthreads();
    float mu = bc[0], rstd = bc[1];
    for (int i = tid; i < HID; i += 256) {
        y[(size_t)r*HID + i] = __float2half_rn((row[i] - mu) * rstd * g[i] + b[i]);
    }
}

// ---------------- fused transpose of all 4 weights ([K][N]->[N][K], fp16) ----
#define TG0 (108*36)
#define TG1 (36*36)
#define TG2 (135*36)
#define TG3 (36*135)
#define TG_ALL (TG0+TG1+TG2+TG3)

__global__ void transpose_all(const float* __restrict__ i0, __half* __restrict__ o0,
                              const float* __restrict__ i1, __half* __restrict__ o1,
                              const float* __restrict__ i2, __half* __restrict__ o2,
                              const float* __restrict__ i3, __half* __restrict__ o3) {
    __shared__ float t[32][33];
    int id = blockIdx.x;
    const float* in; __half* out; int K, N, out_ld, nx;
    if (id < TG0)            { in=i0; out=o0; K=HID;     N=QKV_N;   out_ld=HID;    nx=108; }
    else if (id < TG0+TG1)   { id-=TG0;         in=i1; out=o1; K=HID;     N=HID;     out_ld=HID;    nx=36; }
    else if (id < TG0+TG1+TG2){ id-=TG0+TG1;    in=i2; out=o2; K=HID;     N=MLP_DIM; out_ld=HID;    nx=135; }
    else                     { id-=TG0+TG1+TG2; in=i3; out=o3; K=MLP_DIM; N=HID;     out_ld=MLP_P2; nx=36; }
    int kb = (id/nx)*32, nb = (id%nx)*32;
    int x = threadIdx.x, y = threadIdx.y;
#pragma unroll
    for (int i = 0; i < 32; i += 8) {
        int k = kb + y + i, n = nb + x;
        t[y+i][x] = (k < K && n < N) ? in[(size_t)k*N + n] : 0.f;
    }
    __syncthreads();
#pragma unroll
    for (int i = 0; i < 32; i += 8) {
        int n = nb + y + i, k = kb + x;
        if (n < N && k < K) out[(size_t)n*out_ld + k] = __float2half_rn(t[x][y+i]);
    }
}

// ---------------- v prep: V section of qkvh -> Vt [h][d][tok] ---------------
#define VS_P 82
__global__ void v_prep(const __half* __restrict__ qkv, __half* __restrict__ Vt) {
    __shared__ __half vs[128*VS_P];
    int tid = threadIdx.x;
    int h = blockIdx.y, t0 = blockIdx.x*128;
    for (int t = tid; t < 128*9; t += 256) {
        int row = t/9, ch = t - row*9;
        int d0 = ch*8;
        uint4 raw = *(const uint4*)&qkv[(size_t)(t0+row)*QKV_N + 2*HID + h*HD + d0];
        uint32_t* w = (uint32_t*)&vs[row*VS_P + d0];
        w[0] = raw.x; w[1] = raw.y; w[2] = raw.z; w[3] = raw.w;
    }
    __syncthreads();
    for (int t = tid; t < HD*16; t += 256) {
        int d = t >> 4, cg = t & 15;
        int tok = cg*8;
        __half tmp[8];
#pragma unroll
        for (int i = 0; i < 8; i++) tmp[i] = vs[(tok+i)*VS_P + d];
        *(uint4*)&Vt[((size_t)h*HD + d)*S_TOK + t0 + tok] = *(uint4*)tmp;
    }
}

// ---------------- fp16 GEMM 128x128, 3-stage cp.async -----------------------
// mode 0: bias fp32; 1: bias+residual fp32; 2: bias+gelu fp16; 3: bias fp16;
// mode 4: QKV fused rope -> Qr/Kr (fp16), V -> Cv fp16
#define GBK 64
#define TILE_B (128*128)
#define STAGE_B (2*TILE_B)
#define NSTAGE 3
#define GEMM_SMEM (NSTAGE*STAGE_B)   // 98304

__global__ void __launch_bounds__(256, 2)
hgemm(const __half* __restrict__ A, int ldA,
      const __half* __restrict__ Bt, int ldB,
      const float* __restrict__ bias, const float* __restrict__ residual,
      void* __restrict__ Cv, int ldC, int N, int NIT, int mode,
      const float* __restrict__ fc, __half* __restrict__ outQ,
      __half* __restrict__ outK) {
    extern __shared__ char smg[];
    unsigned sbase = smem_u32(smg);
    int tid = threadIdx.x, warp = tid >> 5, lane = tid & 31;
    int g = lane >> 2, tg = lane & 3;
    int wy = warp >> 1, wx = warp & 1;
    int m0 = blockIdx.y*128, n0 = blockIdx.x*128;

    float c[2][8][4];
#pragma unroll
    for (int mt = 0; mt < 2; mt++)
#pragma unroll
        for (int nt = 0; nt < 8; nt++)
#pragma unroll
            for (int i = 0; i < 4; i++) c[mt][nt][i] = 0.f;

    auto stage = [&](int it, int buf) {
        int k0 = it*GBK;
        unsigned sA = sbase + buf*STAGE_B;
        unsigned sB = sA + TILE_B;
#pragma unroll
        for (int i = 0; i < 4; i++) {
            int t = tid + i*256;
            int row = t >> 3, ch = t & 7;
            unsigned off = (unsigned)(row*128) + ((unsigned)(ch ^ (row & 7)) << 4);
            cp_async16(sA + off, A + (size_t)(m0+row)*ldA + k0 + ch*8, true);
            int n = n0 + row;
            bool v = (n < N);
            cp_async16(sB + off, Bt + (size_t)(v ? n : 0)*ldB + k0 + ch*8, v);
        }
    };

    stage(0, 0); CP_COMMIT;
    if (NIT > 1) stage(1, 1);
    CP_COMMIT;

    unsigned hi = (unsigned)(lane >> 4);
    unsigned aoff[2], amask[2], boff[4], bmask[4];
#pragma unroll
    for (int mt = 0; mt < 2; mt++) {
        int r = wy*32 + mt*16 + (lane & 15);
        aoff[mt] = (unsigned)(r*128); amask[mt] = (unsigned)(r & 7);
    }
#pragma unroll
    for (int p = 0; p < 4; p++) {
        int r = wx*64 + p*16 + (lane & 15);
        boff[p] = (unsigned)(r*128); bmask[p] = (unsigned)(r & 7);
    }

    for (int it = 0; it < NIT; it++) {
        CP_WAIT1;
        __syncthreads();
        if (it + 2 < NIT) stage(it+2, (it+2)%NSTAGE);
        CP_COMMIT;
        unsigned sA = sbase + (it%NSTAGE)*STAGE_B;
        unsigned sB = sA + TILE_B;
#pragma unroll
        for (int s = 0; s < 4; s++) {
            unsigned ci = (unsigned)(s*2) + hi;
            unsigned a[2][4], b[4][4];
#pragma unroll
            for (int mt = 0; mt < 2; mt++)
                LDSM_X4(a[mt], sA + aoff[mt] + ((ci ^ amask[mt]) << 4));
#pragma unroll
            for (int p = 0; p < 4; p++)
                LDSM_X4(b[p], sB + boff[p] + ((ci ^ bmask[p]) << 4));
#pragma unroll
            for (int mt = 0; mt < 2; mt++)
#pragma unroll
                for (int p = 0; p < 4; p++) {
                    MMA_F16(c[mt][2*p],   a[mt], b[p][0], b[p][2]);
                    MMA_F16(c[mt][2*p+1], a[mt], b[p][1], b[p][3]);
                }
        }
    }

    float* Cf = (float*)Cv;
    __half* Ch = (__half*)Cv;
#pragma unroll
    for (int mt = 0; mt < 2; mt++) {
        int row0 = m0 + wy*32 + mt*16 + g;
#pragma unroll
        for (int nt = 0; nt < 8; nt++) {
            int col = n0 + wx*64 + nt*8 + tg*2;
            if (col >= N) continue;
#pragma unroll
            for (int hf = 0; hf < 2; hf++) {
                int r = row0 + hf*8;
                float v0 = c[mt][nt][hf*2+0] + bias[col];
                float v1 = c[mt][nt][hf*2+1] + bias[col+1];
                if (mode == 1) {
                    v0 += residual[(size_t)r*ldC + col];
                    v1 += residual[(size_t)r*ldC + col + 1];
                    *(float2*)&Cf[(size_t)r*ldC + col] = make_float2(v0, v1);
                } else if (mode == 2) {
                    *(__half2*)&Ch[(size_t)r*ldC + col] =
                        __floats2half2_rn(gelu_fast(v0), gelu_fast(v1));
                } else if (mode == 3) {
                    *(__half2*)&Ch[(size_t)r*ldC + col] = __floats2half2_rn(v0, v1);
                } else if (mode == 4) {
                    if (col < 2*HID) {
                        int which = (col >= HID) ? 1 : 0;
                        int cc = col - which*HID;
                        int hh = cc / HD, d0 = cc - hh*HD;   // d0 even
                        float2 cs = *(const float2*)&fc[(size_t)r*HD + d0];
                        float o0 = v0*cs.x - v1*cs.y;
                        float o1 = v0*cs.y + v1*cs.x;
                        __half* dst = which ? outK : outQ;
                        *(__half2*)&dst[((size_t)hh*S_TOK + r)*80 + d0] =
                            __floats2half2_rn(o0, o1);
                    } else {
                        *(__half2*)&Ch[(size_t)r*ldC + col] = __floats2half2_rn(v0, v1);
                    }
                } else {
                    *(float2*)&Cf[(size_t)r*ldC + col] = make_float2(v0, v1);
                }
            }
        }
    }
}

// ---------------- attention: double-buffered K/V + segk, 2 syncs/iter -------
#define AQ2 128
#define AK2 64
#define QKS_H 88
#define PVS_H 72
#define KBUF_H (AK2*QKS_H)
#define VBUF_H (HD*PVS_H)

__device__ __forceinline__ int seg_of(int t, const int* offs) {
    int s = 0;
#pragma unroll
    for (int i = 1; i <= 6; i++) if (offs[i] <= t) s = i;
    return s;
}

#define ATTN_SMEM ((AQ2*QKS_H + 2*KBUF_H + 2*VBUF_H + AQ2*PVS_H)*2 + (128+8)*4)

__global__ void __launch_bounds__(256)
attn2_kernel(const __half* __restrict__ Qr, const __half* __restrict__ Kr,
             const __half* __restrict__ Vt, const int* __restrict__ offs,
             __half* __restrict__ out) {
    extern __shared__ char sm[];
    __half* Qh = (__half*)sm;
    __half* Ph = Qh + AQ2*QKS_H + 2*KBUF_H + 2*VBUF_H;
    int* segk  = (int*)(Ph + AQ2*PVS_H);   // [2][64]
    int* soffs = segk + 128;

    unsigned sbase = smem_u32(sm);
    unsigned uQ = sbase;
    unsigned uK = uQ + AQ2*QKS_H*2;
    unsigned uV = uK + 2*KBUF_H*2;
    unsigned uP = uV + 2*VBUF_H*2;

    int tid = threadIdx.x, warp = tid >> 5, lane = tid & 31;
    int g = lane >> 2, tg = lane & 3;
    int h = blockIdx.y, q0 = blockIdx.x*AQ2;

    if (tid < 7) soffs[tid] = offs[tid];

    auto stageKV = [&](int j0, int buf) {
        const __half* ksrc = Kr + ((size_t)h*S_TOK + j0)*80;
        unsigned kd = uK + (unsigned)buf*KBUF_H*2;
        for (int t = tid; t < AK2*10; t += 256) {
            int row = t/10, ch = t - row*10;
            cp_async16(kd + (unsigned)(row*QKS_H*2 + ch*16), ksrc + row*80 + ch*8, true);
        }
        const __half* vsrc = Vt + (size_t)h*HD*S_TOK + j0;
        unsigned vd = uV + (unsigned)buf*VBUF_H*2;
        for (int t = tid; t < HD*8; t += 256) {
            int d = t >> 3, cg = t & 7;
            cp_async16(vd + (unsigned)(d*PVS_H*2 + cg*16), vsrc + (size_t)d*S_TOK + cg*8, true);
        }
    };

    {
        const __half* qsrc = Qr + ((size_t)h*S_TOK + q0)*80;
        for (int t = tid; t < AQ2*10; t += 256) {
            int row = t/10, ch = t - row*10;
            cp_async16(uQ + (unsigned)(row*QKS_H*2 + ch*16), qsrc + row*80 + ch*8, true);
        }
        stageKV(0, 0);
        CP_COMMIT;
    }
    __syncthreads();   // soffs visible
    if (tid < 64) segk[tid] = seg_of(tid, soffs);   // segk[0] for tile 0

    int r1 = warp*16 + g, r2 = r1 + 8;
    int sq1 = seg_of(q0 + r1, soffs);
    int sq2 = seg_of(q0 + r2, soffs);

    float m1 = -1e30f, m2 = -1e30f, l1 = 0.f, l2 = 0.f;
    float co[9][4];
#pragma unroll
    for (int nt = 0; nt < 9; nt++)
#pragma unroll
        for (int i = 0; i < 4; i++) co[nt][i] = 0.f;

    unsigned hi = (unsigned)(lane >> 4);
    unsigned offQ = (unsigned)((warp*16 + (lane & 15))*QKS_H*2) + hi*16;
    unsigned offP = (unsigned)((warp*16 + (lane & 15))*PVS_H*2) + hi*16;
    unsigned offK[4], offV[4];
#pragma unroll
    for (int p = 0; p < 4; p++) {
        offK[p] = (unsigned)((p*16 + (lane & 15))*QKS_H*2) + hi*16;
        offV[p] = (unsigned)((p*16 + (lane & 15))*PVS_H*2) + hi*16;
    }
    unsigned offV8 = (unsigned)((64 + (lane & 7))*PVS_H*2) + ((unsigned)((lane >> 3) & 1))*16;

    const float scale = 0.11785113019775793f;   // 1/sqrt(72)
    const int NIT = S_TOK/AK2;

    for (int it = 0; it < NIT; it++) {
        int j0 = it*AK2;
        int b0 = it & 1, b1 = b0 ^ 1;
        CP_WAIT0;            // prefetch from previous iter (fully overlapped)
        __syncthreads();     // data visible; prev compute done; segk[b0] visible
        if (it + 1 < NIT) {
            stageKV(j0 + AK2, b1);
            if (tid < 64) segk[b1*64 + tid] = seg_of(j0 + AK2 + tid, soffs);
            CP_COMMIT;
        }

        unsigned uKb = uK + (unsigned)b0*KBUF_H*2;
        unsigned uVb = uV + (unsigned)b0*VBUF_H*2;
        const int* sk = segk + b0*64;

        float sc[8][4];
#pragma unroll
        for (int nt = 0; nt < 8; nt++)
#pragma unroll
            for (int i = 0; i < 4; i++) sc[nt][i] = 0.f;
#pragma unroll
        for (int s = 0; s < 5; s++) {
            unsigned a[4], b[4][4];
            LDSM_X4(a, uQ + offQ + s*32);
#pragma unroll
            for (int p = 0; p < 4; p++) LDSM_X4(b[p], uKb + offK[p] + s*32);
#pragma unroll
            for (int p = 0; p < 4; p++) {
                MMA_F16(sc[2*p],   a, b[p][0], b[p][2]);
                MMA_F16(sc[2*p+1], a, b[p][1], b[p][3]);
            }
        }
        float mx1 = -1e30f, mx2 = -1e30f;
#pragma unroll
        for (int nt = 0; nt < 8; nt++) {
            int col = nt*8 + tg*2;
            int k0s = sk[col], k1s = sk[col+1];
            sc[nt][0] = sc[nt][0]*scale + (sq1 == k0s ? 1.f : 0.f);
            sc[nt][1] = sc[nt][1]*scale + (sq1 == k1s ? 1.f : 0.f);
            sc[nt][2] = sc[nt][2]*scale + (sq2 == k0s ? 1.f : 0.f);
            sc[nt][3] = sc[nt][3]*scale + (sq2 == k1s ? 1.f : 0.f);
            mx1 = fmaxf(mx1, fmaxf(sc[nt][0], sc[nt][1]));
            mx2 = fmaxf(mx2, fmaxf(sc[nt][2], sc[nt][3]));
        }
        mx1 = fmaxf(mx1, __shfl_xor_sync(0xffffffffu, mx1, 1, 4));
        mx1 = fmaxf(mx1, __shfl_xor_sync(0xffffffffu, mx1, 2, 4));
        mx2 = fmaxf(mx2, __shfl_xor_sync(0xffffffffu, mx2, 1, 4));
        mx2 = fmaxf(mx2, __shfl_xor_sync(0xffffffffu, mx2, 2, 4));
        float mn1 = fmaxf(m1, mx1), mn2 = fmaxf(m2, mx2);
        float f1 = __expf(m1 - mn1), f2 = __expf(m2 - mn2);
        m1 = mn1; m2 = mn2;
        float s1 = 0.f, s2 = 0.f;
#pragma unroll
        for (int nt = 0; nt < 8; nt++) {
            float p0 = __expf(sc[nt][0] - m1);
            float p1 = __expf(sc[nt][1] - m1);
            float p2 = __expf(sc[nt][2] - m2);
            float p3 = __expf(sc[nt][3] - m2);
            s1 += p0 + p1; s2 += p2 + p3;
            int col = nt*8 + tg*2;
            *(__half2*)&Ph[r1*PVS_H + col] = __floats2half2_rn(p0, p1);
            *(__half2*)&Ph[r2*PVS_H + col] = __floats2half2_rn(p2, p3);
        }
        s1 += __shfl_xor_sync(0xffffffffu, s1, 1, 4);
        s1 += __shfl_xor_sync(0xffffffffu, s1, 2, 4);
        s2 += __shfl_xor_sync(0xffffffffu, s2, 1, 4);
        s2 += __shfl_xor_sync(0xffffffffu, s2, 2, 4);
        l1 = l1*f1 + s1; l2 = l2*f2 + s2;
#pragma unroll
        for (int nt = 0; nt < 9; nt++) {
            co[nt][0] *= f1; co[nt][1] *= f1;
            co[nt][2] *= f2; co[nt][3] *= f2;
        }
        __syncthreads();     // P visible
#pragma unroll
        for (int s = 0; s < 4; s++) {
            unsigned a[4], b[4][4], b8[2];
            LDSM_X4(a, uP + offP + s*32);
#pragma unroll
            for (int p = 0; p < 4; p++) LDSM_X4(b[p], uVb + offV[p] + s*32);
            LDSM_X2(b8, uVb + offV8 + s*32);
#pragma unroll
            for (int p = 0; p < 4; p++) {
                MMA_F16(co[2*p],   a, b[p][0], b[p][2]);
                MMA_F16(co[2*p+1], a, b[p][1], b[p][3]);
            }
            MMA_F16(co[8], a, b8[0], b8[1]);
        }
    }

    float i1 = 1.f/l1, i2 = 1.f/l2;
#pragma unroll
    for (int nt = 0; nt < 9; nt++) {
        int d0 = nt*8 + tg*2;
        *(__half2*)&out[(size_t)(q0+r1)*HID + h*HD + d0] =
            __floats2half2_rn(co[nt][0]*i1, co[nt][1]*i1);
        *(__half2*)&out[(size_t)(q0+r2)*HID + h*HD + d0] =
            __floats2half2_rn(co[nt][2]*i2, co[nt][3]*i2);
    }
}

// ---------------- launch ----------------
extern "C" void kernel_launch(void* const* d_in, const int* in_sizes, int n_in,
                              void* d_out, int out_size) {
    const float* x      = (const float*)d_in[0];
    const int*   offs   = (const int*)  d_in[1];
    const float* fc     = (const float*)d_in[2];
    const float* ln0_g  = (const float*)d_in[3];
    const float* ln0_b  = (const float*)d_in[4];
    const float* wqkv_w = (const float*)d_in[5];
    const float* wqkv_b = (const float*)d_in[6];
    const float* wo_w   = (const float*)d_in[7];
    const float* wo_b   = (const float*)d_in[8];
    const float* ln1_g  = (const float*)d_in[9];
    const float* ln1_b  = (const float*)d_in[10];
    const float* w1     = (const float*)d_in[11];
    const float* b1     = (const float*)d_in[12];
    const float* w2     = (const float*)d_in[13];
    const float* b2     = (const float*)d_in[14];
    float* out = (float*)d_out;

    float *x2;
    __half *qkvh, *Qr, *Kr, *Vt, *h0h, *attnh, *h1h, *mlph;
    __half *wqkvth, *woth, *w1th, *w2th;
    cudaGetSymbolAddress((void**)&x2,     g_x2);
    cudaGetSymbolAddress((void**)&qkvh,   g_qkvh);
    cudaGetSymbolAddress((void**)&Qr,     g_Qr);
    cudaGetSymbolAddress((void**)&Kr,     g_Kr);
    cudaGetSymbolAddress((void**)&Vt,     g_Vt);
    cudaGetSymbolAddress((void**)&h0h,    g_h0h);
    cudaGetSymbolAddress((void**)&attnh,  g_attnh);
    cudaGetSymbolAddress((void**)&h1h,    g_h1h);
    cudaGetSymbolAddress((void**)&mlph,   g_mlph);
    cudaGetSymbolAddress((void**)&wqkvth, g_wqkvth);
    cudaGetSymbolAddress((void**)&woth,   g_woth);
    cudaGetSymbolAddress((void**)&w1th,   g_w1th);
    cudaGetSymbolAddress((void**)&w2th,   g_w2th);

    cudaFuncSetAttribute(hgemm, cudaFuncAttributeMaxDynamicSharedMemorySize, GEMM_SMEM);
    cudaFuncSetAttribute(attn2_kernel, cudaFuncAttributeMaxDynamicSharedMemorySize, ATTN_SMEM);

    // 0. fused weight transposes -> [N][K] fp16
    transpose_all<<<TG_ALL, dim3(32,8)>>>(wqkv_w, wqkvth, wo_w, woth, w1, w1th, w2, w2th);

    // 1. LN0 -> fp16
    ln_kernel<<<S_TOK, 256>>>(x, ln0_g, ln0_b, h0h);
    // 2. QKV GEMM with fused rope epilogue: Q/K -> Qr/Kr, V -> qkvh
    hgemm<<<dim3(QKV_N/128, S_TOK/128), 256, GEMM_SMEM>>>(
        h0h, HID, wqkvth, HID, wqkv_b, nullptr, qkvh, QKV_N, QKV_N, HID/GBK, 4,
        fc, Qr, Kr);
    // 3. V transpose prep
    v_prep<<<dim3(S_TOK/128, NH), 256>>>(qkvh, Vt);
    // 4. attention -> fp16
    attn2_kernel<<<dim3(S_TOK/AQ2, NH), 256, ATTN_SMEM>>>(Qr, Kr, Vt, offs, attnh);
    // 5. x2 = x + attn @ wo + b  (fp32 out)
    hgemm<<<dim3(HID/128, S_TOK/128), 256, GEMM_SMEM>>>(
        attnh, HID, woth, HID, wo_b, x, x2, HID, HID, HID/GBK, 1,
        nullptr, nullptr, nullptr);
    // 6. LN1 -> fp16
    ln_kernel<<<S_TOK, 256>>>(x2, ln1_g, ln1_b, h1h);
    // 7. mlp = gelu(h1 @ w1 + b1) -> fp16
    hgemm<<<dim3((MLP_DIM+127)/128, S_TOK/128), 256, GEMM_SMEM>>>(
        h1h, HID, w1th, HID, b1, nullptr, mlph, MLP_P2, MLP_DIM, HID/GBK, 2,
        nullptr, nullptr, nullptr);
    // 8. out = x2 + mlp @ w2 + b2
    hgemm<<<dim3(HID/128, S_TOK/128), 256, GEMM_SMEM>>>(
        mlph, MLP_P2, w2th, MLP_P2, b2, x2, out, HID, HID, MLP_P2/GBK, 1,
        nullptr, nullptr, nullptr);
}